// round 1
// baseline (speedup 1.0000x reference)
#include <cuda_runtime.h>
#include <math.h>

#define NB   8192
#define NA   32
#define NOBS 128
#define NH1  128
#define NHX  64
#define NACT 16

#define BT   64
#define PAD  65   // padded row stride for transposed activation tiles (conflict-free)

// Scratch (allocation-free rule: __device__ globals)
__device__ float g_h[NB * NA * NHX];      // 64 MB
__device__ float g_comm[NB * NA * NHX];   // 64 MB
__device__ float g_maskn[NA * NA];

// ---------------------------------------------------------------------------
// Normalized communication matrix: M[i][j] = offdiag_mask / max(count_i, 1)
// ---------------------------------------------------------------------------
__global__ void k_mask(const int* __restrict__ cm) {
    int i = threadIdx.x;
    if (i >= NA) return;
    int cnt = 0;
#pragma unroll
    for (int j = 0; j < NA; j++)
        cnt += (j != i && cm[i * NA + j] != 0) ? 1 : 0;
    float inv = 1.0f / (float)(cnt > 0 ? cnt : 1);
#pragma unroll
    for (int j = 0; j < NA; j++)
        g_maskn[i * NA + j] = (j != i && cm[i * NA + j] != 0) ? inv : 0.0f;
}

// ---------------------------------------------------------------------------
// Encoder: h = relu(relu(obs@W1 + b1)@W2 + b2), per (batch-tile, agent) block
// smem: Ws (W1 then W2, 64KB) | aT (obsT then xT, 128 x PAD) | bias
// ---------------------------------------------------------------------------
__global__ __launch_bounds__(256, 2) void k_encode(
    const float* __restrict__ obs,
    const float* __restrict__ W1, const float* __restrict__ b1,
    const float* __restrict__ W2, const float* __restrict__ b2)
{
    extern __shared__ float sm[];
    float* Ws   = sm;                       // 128*128 floats
    float* aT   = sm + NH1 * NOBS;          // 128 x PAD
    float* bias = aT + NOBS * PAD;          // 128

    const int tid = threadIdx.x;
    const int b0  = blockIdx.x * BT;
    const int a   = blockIdx.y;

    // Stage W1 [128][128] (row-major [k][n], matches smem layout)
    {
        const float4* src = (const float4*)(W1 + a * NOBS * NH1);
        float4* dst = (float4*)Ws;
#pragma unroll
        for (int i = tid; i < NOBS * NH1 / 4; i += 256) dst[i] = src[i];
    }
    // Stage obs transposed: aT[k][m] = obs[b0+m][a][k]
    for (int i = tid; i < BT * NOBS / 4; i += 256) {
        int m  = i >> 5;          // 32 float4 per row of 128
        int kq = i & 31;
        float4 v = *(const float4*)(obs + ((b0 + m) * NA + a) * NOBS + kq * 4);
        int k = kq * 4;
        aT[(k + 0) * PAD + m] = v.x;
        aT[(k + 1) * PAD + m] = v.y;
        aT[(k + 2) * PAD + m] = v.z;
        aT[(k + 3) * PAD + m] = v.w;
    }
    if (tid < NH1) bias[tid] = b1[a * NH1 + tid];
    __syncthreads();

    const int tm = tid >> 5;   // 0..7  -> rows m = tm*8 .. tm*8+7
    const int tn = tid & 31;   // 0..31 -> cols n = tn + j*32

    // GEMM1: x[64][128] = obsT^T @ W1
    float acc[8][4];
#pragma unroll
    for (int i = 0; i < 8; i++)
#pragma unroll
        for (int j = 0; j < 4; j++) acc[i][j] = 0.0f;

#pragma unroll 4
    for (int k = 0; k < NOBS; k++) {
        float av[8], bv[4];
#pragma unroll
        for (int i = 0; i < 8; i++) av[i] = aT[k * PAD + tm * 8 + i];
#pragma unroll
        for (int j = 0; j < 4; j++) bv[j] = Ws[k * NH1 + tn + j * 32];
#pragma unroll
        for (int i = 0; i < 8; i++)
#pragma unroll
            for (int j = 0; j < 4; j++) acc[i][j] += av[i] * bv[j];
    }
    // bias + relu (reads bias before it is overwritten)
#pragma unroll
    for (int j = 0; j < 4; j++) {
        float bb = bias[tn + j * 32];
#pragma unroll
        for (int i = 0; i < 8; i++) acc[i][j] = fmaxf(acc[i][j] + bb, 0.0f);
    }
    __syncthreads();

    // Store xT[n][m] into aT (pad-65: stride-1 across tn -> conflict-free)
#pragma unroll
    for (int j = 0; j < 4; j++)
#pragma unroll
        for (int i = 0; i < 8; i++)
            aT[(tn + j * 32) * PAD + tm * 8 + i] = acc[i][j];

    // Stage W2 [128][64] and b2
    {
        const float4* src = (const float4*)(W2 + a * NH1 * NHX);
        float4* dst = (float4*)Ws;
#pragma unroll
        for (int i = tid; i < NH1 * NHX / 4; i += 256) dst[i] = src[i];
    }
    if (tid < NHX) bias[tid] = b2[a * NHX + tid];
    __syncthreads();

    // GEMM2: h[64][64] = xT^T @ W2
    float acc2[8][2];
#pragma unroll
    for (int i = 0; i < 8; i++)
#pragma unroll
        for (int j = 0; j < 2; j++) acc2[i][j] = 0.0f;

#pragma unroll 4
    for (int k = 0; k < NH1; k++) {
        float av[8], bv[2];
#pragma unroll
        for (int i = 0; i < 8; i++) av[i] = aT[k * PAD + tm * 8 + i];
#pragma unroll
        for (int j = 0; j < 2; j++) bv[j] = Ws[k * NHX + tn + j * 32];
#pragma unroll
        for (int i = 0; i < 8; i++)
#pragma unroll
            for (int j = 0; j < 2; j++) acc2[i][j] += av[i] * bv[j];
    }
#pragma unroll
    for (int j = 0; j < 2; j++) {
        float bb = bias[tn + j * 32];
#pragma unroll
        for (int i = 0; i < 8; i++) {
            float v = fmaxf(acc2[i][j] + bb, 0.0f);
            g_h[((b0 + tm * 8 + i) * NA + a) * NHX + tn + j * 32] = v;
        }
    }
}

// ---------------------------------------------------------------------------
// Communication: comm[b,i,:] = sum_j M[i,j] * h[b,j,:]
// One block per batch row b; warp w handles agents i0..i0+3; Ms via shuffle.
// ---------------------------------------------------------------------------
__global__ __launch_bounds__(256) void k_comm() {
    __shared__ float hs[NA * NHX];  // 2048 floats
    const int tid = threadIdx.x;
    const int b = blockIdx.x;

    {
        const float4* src = (const float4*)(g_h + (size_t)b * NA * NHX);
        float4* dst = (float4*)hs;
#pragma unroll
        for (int i = tid; i < NA * NHX / 4; i += 256) dst[i] = src[i];
    }
    __syncthreads();

    const int lane = tid & 31;
    const int ig   = tid >> 5;     // 0..7
    const int i0   = ig * 4;

    float mreg[4];
#pragma unroll
    for (int ii = 0; ii < 4; ii++) mreg[ii] = g_maskn[(i0 + ii) * NA + lane];

    float acc[4][2];
#pragma unroll
    for (int ii = 0; ii < 4; ii++) { acc[ii][0] = 0.0f; acc[ii][1] = 0.0f; }

#pragma unroll
    for (int j = 0; j < NA; j++) {
        float h0 = hs[j * NHX + lane];
        float h1 = hs[j * NHX + lane + 32];
#pragma unroll
        for (int ii = 0; ii < 4; ii++) {
            float mj = __shfl_sync(0xffffffffu, mreg[ii], j);
            acc[ii][0] += mj * h0;
            acc[ii][1] += mj * h1;
        }
    }
#pragma unroll
    for (int ii = 0; ii < 4; ii++) {
        g_comm[((size_t)b * NA + i0 + ii) * NHX + lane]      = acc[ii][0];
        g_comm[((size_t)b * NA + i0 + ii) * NHX + lane + 32] = acc[ii][1];
    }
}

// ---------------------------------------------------------------------------
// Final: h2 = tanh([h, comm]@Wc + bc); q = h2@Wd + bd
// ---------------------------------------------------------------------------
__global__ __launch_bounds__(256, 2) void k_final(
    const float* __restrict__ Wc, const float* __restrict__ bc,
    const float* __restrict__ Wd, const float* __restrict__ bd,
    float* __restrict__ q)
{
    extern __shared__ float sm[];
    float* Ws  = sm;                        // Wc: 128*64
    float* aT  = sm + 2 * NHX * NHX;        // 128 x PAD (concat input, then h2T in rows 0..63)
    float* Wds = aT + 2 * NHX * PAD;        // 64*16
    float* bcs = Wds + NHX * NACT;          // 64
    float* bds = bcs + NHX;                 // 16

    const int tid = threadIdx.x;
    const int b0  = blockIdx.x * BT;
    const int a   = blockIdx.y;

    // Stage Wc [128][64]
    {
        const float4* src = (const float4*)(Wc + a * 2 * NHX * NHX);
        float4* dst = (float4*)Ws;
#pragma unroll
        for (int i = tid; i < 2 * NHX * NHX / 4; i += 256) dst[i] = src[i];
    }
    // Stage concat input transposed: rows 0..63 = h, rows 64..127 = comm
    for (int i = tid; i < BT * NHX / 4; i += 256) {
        int m  = i >> 4;          // 16 float4 per 64-float row
        int kq = i & 15;
        int c = kq * 4;
        float4 v = *(const float4*)(g_h    + ((size_t)(b0 + m) * NA + a) * NHX + kq * 4);
        float4 w = *(const float4*)(g_comm + ((size_t)(b0 + m) * NA + a) * NHX + kq * 4);
        aT[(c + 0) * PAD + m] = v.x;  aT[(c + 1) * PAD + m] = v.y;
        aT[(c + 2) * PAD + m] = v.z;  aT[(c + 3) * PAD + m] = v.w;
        aT[(NHX + c + 0) * PAD + m] = w.x;  aT[(NHX + c + 1) * PAD + m] = w.y;
        aT[(NHX + c + 2) * PAD + m] = w.z;  aT[(NHX + c + 3) * PAD + m] = w.w;
    }
    // Stage Wd [64][16], biases
    {
        const float4* src = (const float4*)(Wd + a * NHX * NACT);
        float4* dst = (float4*)Wds;
#pragma unroll
        for (int i = tid; i < NHX * NACT / 4; i += 256) dst[i] = src[i];
    }
    if (tid < NHX)  bcs[tid] = bc[a * NHX + tid];
    if (tid < NACT) bds[tid] = bd[a * NACT + tid];
    __syncthreads();

    const int tm = tid >> 5;
    const int tn = tid & 31;

    // GEMM3: pre[64][64] = concat^T @ Wc
    float acc[8][2];
#pragma unroll
    for (int i = 0; i < 8; i++)
#pragma unroll
        for (int j = 0; j < 2; j++) acc[i][j] = 0.0f;

#pragma unroll 4
    for (int k = 0; k < 2 * NHX; k++) {
        float av[8], bv[2];
#pragma unroll
        for (int i = 0; i < 8; i++) av[i] = aT[k * PAD + tm * 8 + i];
#pragma unroll
        for (int j = 0; j < 2; j++) bv[j] = Ws[k * NHX + tn + j * 32];
#pragma unroll
        for (int i = 0; i < 8; i++)
#pragma unroll
            for (int j = 0; j < 2; j++) acc[i][j] += av[i] * bv[j];
    }
#pragma unroll
    for (int j = 0; j < 2; j++) {
        float bb = bcs[tn + j * 32];
#pragma unroll
        for (int i = 0; i < 8; i++) acc[i][j] = tanhf(acc[i][j] + bb);
    }
    __syncthreads();

    // h2T[n][m] into aT rows 0..63
#pragma unroll
    for (int j = 0; j < 2; j++)
#pragma unroll
        for (int i = 0; i < 8; i++)
            aT[(tn + j * 32) * PAD + tm * 8 + i] = acc[i][j];
    __syncthreads();

    // GEMM4: q[64][16] = h2 @ Wd  (thread: m = tid&63, n-group = tid>>6)
    const int m = tid & 63;
    const int g = tid >> 6;
    float acc3[4] = {0.0f, 0.0f, 0.0f, 0.0f};
#pragma unroll
    for (int k = 0; k < NHX; k++) {
        float av = aT[k * PAD + m];
#pragma unroll
        for (int jj = 0; jj < 4; jj++) acc3[jj] += av * Wds[k * NACT + g * 4 + jj];
    }
    float4 outv;
    outv.x = acc3[0] + bds[g * 4 + 0];
    outv.y = acc3[1] + bds[g * 4 + 1];
    outv.z = acc3[2] + bds[g * 4 + 2];
    outv.w = acc3[3] + bds[g * 4 + 3];
    *(float4*)(q + ((size_t)(b0 + m) * NA + a) * NACT + g * 4) = outv;
}

// ---------------------------------------------------------------------------
extern "C" void kernel_launch(void* const* d_in, const int* in_sizes, int n_in,
                              void* d_out, int out_size) {
    const float* obs = (const float*)d_in[0];
    const float* W1  = (const float*)d_in[1];
    const float* b1  = (const float*)d_in[2];
    const float* W2  = (const float*)d_in[3];
    const float* b2  = (const float*)d_in[4];
    // d_in[5], d_in[6]: Wg, bg — dead code (gates never reach the output)
    const float* Wc  = (const float*)d_in[7];
    const float* bc  = (const float*)d_in[8];
    const float* Wd  = (const float*)d_in[9];
    const float* bd  = (const float*)d_in[10];
    const int*   cm  = (const int*)d_in[11];
    float* q = (float*)d_out;

    const size_t smem_enc = (size_t)(NH1 * NOBS + NOBS * PAD + NH1) * sizeof(float);           // 99328
    const size_t smem_fin = (size_t)(2 * NHX * NHX + 2 * NHX * PAD + NHX * NACT + NHX + NACT) * sizeof(float); // 70464

    cudaFuncSetAttribute(k_encode, cudaFuncAttributeMaxDynamicSharedMemorySize, (int)smem_enc);
    cudaFuncSetAttribute(k_final,  cudaFuncAttributeMaxDynamicSharedMemorySize, (int)smem_fin);

    k_mask<<<1, 32>>>(cm);
    k_encode<<<dim3(NB / BT, NA), 256, smem_enc>>>(obs, W1, b1, W2, b2);
    k_comm<<<NB, 256>>>();
    k_final<<<dim3(NB / BT, NA), 256, smem_fin>>>(Wc, bc, Wd, bd, q);
}